// round 13
// baseline (speedup 1.0000x reference)
#include <cuda_runtime.h>
#include <cstdint>

#define N_FEAT 512
#define N_PAIRS (N_FEAT * (N_FEAT - 1) / 2)   // 130816
#define TB 8              // batch rows per block
#define THREADS 256
#define PPT 4             // pairs per quad
#define N_QUADS (N_PAIRS / 4)    // 32704
#define P_SEG 32                 // p segments
#define QPS (N_QUADS / P_SEG)    // 1022 quads per segment (exact: 32*1022=32704)

// Bank-permutation: feature f stored at word perm(f).
// For lane-stride-4 access (j = j0 + 4*lane), perm(j) mod 32 strides 1 -> conflict-free.
__device__ __forceinline__ int perm(int f) {
    return (f >> 2) | ((f & 3) << 7);
}

__device__ __forceinline__ int tri_off(int i) {
    return (i * (2 * N_FEAT - 1 - i)) >> 1;
}

__device__ __forceinline__ void pair_from_p(int p, int& i, int& j) {
    float t = (float)N_FEAT - 0.5f;
    float d = t * t - 2.0f * (float)p;
    d = d > 0.0f ? d : 0.0f;
    int ii = (int)floorf(t - sqrtf(d));
    if (ii < 0) ii = 0;
    if (ii > N_FEAT - 2) ii = N_FEAT - 2;
    while (ii < N_FEAT - 2 && tri_off(ii + 1) <= p) ii++;
    while (ii > 0 && tri_off(ii) > p) ii--;
    i = ii;
    j = ii + 1 + (p - tri_off(ii));
}

__global__ void __launch_bounds__(THREADS, 8)
wide_layer_kernel(const float* __restrict__ x,
                  const float* __restrict__ w,
                  float* __restrict__ out)
{
    __shared__ float xs[TB * N_FEAT];   // 16 KB, bank-permuted per row

    const int tid = threadIdx.x;
    const int b0  = blockIdx.y * TB;

    // Fill once per block; amortized over the block's 4 quad-chunks.
    {
        const float4* xg = (const float4*)(x + (size_t)b0 * N_FEAT);
        #pragma unroll
        for (int k = 0; k < (TB * N_FEAT / 4) / THREADS; k++) {
            int v = tid + k * THREADS;
            int row = v >> 7;
            int c   = v & 127;
            float4 val = xg[v];
            float* dstp = xs + row * N_FEAT;
            int f = c * 4;
            dstp[perm(f + 0)] = val.x;
            dstp[perm(f + 1)] = val.y;
            dstp[perm(f + 2)] = val.z;
            dstp[perm(f + 3)] = val.w;
        }
    }
    __syncthreads();

    const int q_begin = blockIdx.x * QPS;
    const int q_end   = q_begin + QPS;

    for (int q = q_begin + tid; q < q_end; q += THREADS) {
        const int p0 = q * PPT;

        // per-quad pair plan (pre-permuted smem indices)
        int ip[PPT], jp[PPT];
        {
            int ii, jj;
            pair_from_p(p0, ii, jj);
            #pragma unroll
            for (int k = 0; k < PPT; k++) {
                ip[k] = perm(ii);
                jp[k] = perm(jj);
                jj++;
                if (jj == N_FEAT) { ii++; jj = ii + 1; }
            }
        }
        const bool same = (ip[3] == ip[0]);   // quad within one i row (~98% thr,
                                              // all-lanes-true for ~56% of warps)
        const bool s1   = (ip[1] == ip[0]);
        const bool s2   = (ip[2] == ip[0]);
        const bool odd1 = (ip[1] != ip[0]) && (ip[1] != ip[3]);  // rare 3-row span
        const bool odd2 = (ip[2] != ip[0]) && (ip[2] != ip[3]);

        const float4 w4 = *(const float4*)(w + p0);

        float4* dst = (float4*)(out + (size_t)b0 * N_PAIRS + p0);
        const size_t dstride = N_PAIRS / 4;

        const float* xr = xs;
        #pragma unroll
        for (int b = 0; b < TB; b++) {
            float xia = xr[ip[0]];            // broadcast LDS (1 wf)
            float xib = xia;
            if (!same) xib = xr[ip[3]];       // 0 wf in boundary-free warps
            float x1 = s1 ? xia : xib;
            float x2 = s2 ? xia : xib;
            if (odd1) x1 = xr[ip[1]];         // rare fixup
            if (odd2) x2 = xr[ip[2]];
            float4 o;
            o.x = xia * xr[jp[0]] * w4.x;
            o.y = x1  * xr[jp[1]] * w4.y;
            o.z = x2  * xr[jp[2]] * w4.z;
            o.w = xib * xr[jp[3]] * w4.w;
            __stcs(dst, o);                   // streaming store
            dst += dstride;
            xr  += N_FEAT;
        }
    }
}

extern "C" void kernel_launch(void* const* d_in, const int* in_sizes, int n_in,
                              void* d_out, int out_size)
{
    const float* x = (const float*)d_in[0];
    const float* w = (const float*)d_in[1];
    float* out = (float*)d_out;

    dim3 grid(P_SEG, 1024 / TB);   // 32 x 128 = 4096 blocks (~3.5 waves)
    wide_layer_kernel<<<grid, THREADS>>>(x, w, out);
}

// round 15
// speedup vs baseline: 1.4682x; 1.4682x over previous
#include <cuda_runtime.h>
#include <cstdint>

#define N_FEAT 512
#define N_PAIRS (N_FEAT * (N_FEAT - 1) / 2)   // 130816
#define TB 8              // batch rows per block
#define THREADS 256
#define PPT 4             // pairs per quad
#define N_QUADS (N_PAIRS / 4)    // 32704
#define P_SEG 32                 // p segments
#define QPS (N_QUADS / P_SEG)    // 1022 quads per segment (exact: 32*1022=32704)

// Bank-permutation: feature f stored at word perm(f).
// For lane-stride-4 access (j = j0 + 4*lane), perm(j) mod 32 strides 1 -> conflict-free.
__device__ __forceinline__ int perm(int f) {
    return (f >> 2) | ((f & 3) << 7);
}

__device__ __forceinline__ int tri_off(int i) {
    return (i * (2 * N_FEAT - 1 - i)) >> 1;
}

__device__ __forceinline__ void pair_from_p(int p, int& i, int& j) {
    float t = (float)N_FEAT - 0.5f;
    float d = t * t - 2.0f * (float)p;
    d = d > 0.0f ? d : 0.0f;
    int ii = (int)floorf(t - sqrtf(d));
    if (ii < 0) ii = 0;
    if (ii > N_FEAT - 2) ii = N_FEAT - 2;
    while (ii < N_FEAT - 2 && tri_off(ii + 1) <= p) ii++;
    while (ii > 0 && tri_off(ii) > p) ii--;
    i = ii;
    j = ii + 1 + (p - tri_off(ii));
}

__global__ void __launch_bounds__(THREADS, 8)
wide_layer_kernel(const float* __restrict__ x,
                  const float* __restrict__ w,
                  float* __restrict__ out)
{
    __shared__ float xs[TB * N_FEAT];   // 16 KB, bank-permuted per row

    const int tid = threadIdx.x;
    const int b0  = blockIdx.y * TB;

    // Fill once per block; amortized over the block's ~4 quad-chunks.
    {
        const float4* xg = (const float4*)(x + (size_t)b0 * N_FEAT);
        #pragma unroll
        for (int k = 0; k < (TB * N_FEAT / 4) / THREADS; k++) {
            int v = tid + k * THREADS;
            int row = v >> 7;
            int c   = v & 127;
            float4 val = xg[v];
            float* dstp = xs + row * N_FEAT;
            int f = c * 4;
            dstp[perm(f + 0)] = val.x;
            dstp[perm(f + 1)] = val.y;
            dstp[perm(f + 2)] = val.z;
            dstp[perm(f + 3)] = val.w;
        }
    }
    __syncthreads();

    const int q_begin = blockIdx.x * QPS;
    const int q_end   = q_begin + QPS;

    for (int q = q_begin + tid; q < q_end; q += THREADS) {
        const int p0 = q * PPT;

        // per-quad pair plan (pre-permuted smem indices)
        int ip[PPT], jp[PPT];
        {
            int ii, jj;
            pair_from_p(p0, ii, jj);
            #pragma unroll
            for (int k = 0; k < PPT; k++) {
                ip[k] = perm(ii);
                jp[k] = perm(jj);
                jj++;
                if (jj == N_FEAT) { ii++; jj = ii + 1; }
            }
        }
        const bool s1   = (ip[1] == ip[0]);
        const bool s2   = (ip[2] == ip[0]);
        const bool odd1 = (ip[1] != ip[0]) && (ip[1] != ip[3]);  // rare 3-row span
        const bool odd2 = (ip[2] != ip[0]) && (ip[2] != ip[3]);

        const float4 w4 = *(const float4*)(w + p0);

        float4* dst = (float4*)(out + (size_t)b0 * N_PAIRS + p0);
        const size_t dstride = N_PAIRS / 4;

        const float* xr = xs;
        #pragma unroll
        for (int b = 0; b < TB; b++) {
            float xia = xr[ip[0]];            // broadcast LDS (unconditional)
            float xib = xr[ip[3]];            // broadcast LDS (unconditional)
            float x1 = s1 ? xia : xib;
            float x2 = s2 ? xia : xib;
            if (odd1) x1 = xr[ip[1]];         // rare fixup (cold predicate)
            if (odd2) x2 = xr[ip[2]];
            float4 o;
            o.x = xia * xr[jp[0]] * w4.x;
            o.y = x1  * xr[jp[1]] * w4.y;
            o.z = x2  * xr[jp[2]] * w4.z;
            o.w = xib * xr[jp[3]] * w4.w;
            __stcs(dst, o);                   // streaming store
            dst += dstride;
            xr  += N_FEAT;
        }
    }
}

extern "C" void kernel_launch(void* const* d_in, const int* in_sizes, int n_in,
                              void* d_out, int out_size)
{
    const float* x = (const float*)d_in[0];
    const float* w = (const float*)d_in[1];
    float* out = (float*)d_out;

    dim3 grid(P_SEG, 1024 / TB);   // 32 x 128 = 4096 blocks (~3.5 waves)
    wide_layer_kernel<<<grid, THREADS>>>(x, w, out);
}

// round 16
// speedup vs baseline: 1.5351x; 1.0456x over previous
#include <cuda_runtime.h>
#include <cstdint>

#define N_FEAT 512
#define N_PAIRS (N_FEAT * (N_FEAT - 1) / 2)   // 130816
#define TB 8              // batch rows per block
#define THREADS 512
#define PPT 4             // pairs per quad
#define N_QUADS (N_PAIRS / 4)    // 32704
#define P_SEG 32                 // p segments
#define QPS (N_QUADS / P_SEG)    // 1022 quads per segment (exact: 32*1022=32704)

// Bank-permutation: feature f stored at word perm(f).
// For lane-stride-4 access (j = j0 + 4*lane), perm(j) mod 32 strides 1 -> conflict-free.
__device__ __forceinline__ int perm(int f) {
    return (f >> 2) | ((f & 3) << 7);
}

__device__ __forceinline__ int tri_off(int i) {
    return (i * (2 * N_FEAT - 1 - i)) >> 1;
}

__device__ __forceinline__ void pair_from_p(int p, int& i, int& j) {
    float t = (float)N_FEAT - 0.5f;
    float d = t * t - 2.0f * (float)p;
    d = d > 0.0f ? d : 0.0f;
    int ii = (int)floorf(t - sqrtf(d));
    if (ii < 0) ii = 0;
    if (ii > N_FEAT - 2) ii = N_FEAT - 2;
    while (ii < N_FEAT - 2 && tri_off(ii + 1) <= p) ii++;
    while (ii > 0 && tri_off(ii) > p) ii--;
    i = ii;
    j = ii + 1 + (p - tri_off(ii));
}

__global__ void __launch_bounds__(THREADS, 4)
wide_layer_kernel(const float* __restrict__ x,
                  const float* __restrict__ w,
                  float* __restrict__ out)
{
    __shared__ float xs[TB * N_FEAT];   // 16 KB, bank-permuted per row

    const int tid = threadIdx.x;
    const int b0  = blockIdx.y * TB;

    // Fill once per block; amortized over the block's 1022 quads.
    {
        const float4* xg = (const float4*)(x + (size_t)b0 * N_FEAT);
        #pragma unroll
        for (int k = 0; k < (TB * N_FEAT / 4) / THREADS; k++) {
            int v = tid + k * THREADS;
            int row = v >> 7;
            int c   = v & 127;
            float4 val = xg[v];
            float* dstp = xs + row * N_FEAT;
            int f = c * 4;
            dstp[perm(f + 0)] = val.x;
            dstp[perm(f + 1)] = val.y;
            dstp[perm(f + 2)] = val.z;
            dstp[perm(f + 3)] = val.w;
        }
    }
    __syncthreads();

    const int q_begin = blockIdx.x * QPS;
    const int q_end   = q_begin + QPS;

    for (int q = q_begin + tid; q < q_end; q += THREADS) {
        const int p0 = q * PPT;

        // per-quad pair plan (pre-permuted smem indices)
        int ip[PPT], jp[PPT];
        {
            int ii, jj;
            pair_from_p(p0, ii, jj);
            #pragma unroll
            for (int k = 0; k < PPT; k++) {
                ip[k] = perm(ii);
                jp[k] = perm(jj);
                jj++;
                if (jj == N_FEAT) { ii++; jj = ii + 1; }
            }
        }
        const bool s1   = (ip[1] == ip[0]);
        const bool s2   = (ip[2] == ip[0]);
        const bool odd1 = (ip[1] != ip[0]) && (ip[1] != ip[3]);  // rare 3-row span
        const bool odd2 = (ip[2] != ip[0]) && (ip[2] != ip[3]);

        const float4 w4 = *(const float4*)(w + p0);

        float4* dst = (float4*)(out + (size_t)b0 * N_PAIRS + p0);
        const size_t dstride = N_PAIRS / 4;

        const float* xr = xs;
        #pragma unroll
        for (int b = 0; b < TB; b++) {
            float xia = xr[ip[0]];            // broadcast LDS (unconditional)
            float xib = xr[ip[3]];            // broadcast LDS (unconditional)
            float x1 = s1 ? xia : xib;
            float x2 = s2 ? xia : xib;
            if (odd1) x1 = xr[ip[1]];         // rare fixup (cold predicate)
            if (odd2) x2 = xr[ip[2]];
            float4 o;
            o.x = xia * xr[jp[0]] * w4.x;
            o.y = x1  * xr[jp[1]] * w4.y;
            o.z = x2  * xr[jp[2]] * w4.z;
            o.w = xib * xr[jp[3]] * w4.w;
            __stcs(dst, o);                   // streaming store
            dst += dstride;
            xr  += N_FEAT;
        }
    }
}

extern "C" void kernel_launch(void* const* d_in, const int* in_sizes, int n_in,
                              void* d_out, int out_size)
{
    const float* x = (const float*)d_in[0];
    const float* w = (const float*)d_in[1];
    float* out = (float*)d_out;

    dim3 grid(P_SEG, 1024 / TB);   // 32 x 128 = 4096 blocks of 512 (~6.9 waves)
    wide_layer_kernel<<<grid, THREADS>>>(x, w, out);
}